// round 2
// baseline (speedup 1.0000x reference)
#include <cuda_runtime.h>
#include <math.h>

#define TDIM 16384
#define BDIM 64
#define EDIM 512
#define HIDD 16
#define NROWS 704            // 192 (P~) + 256 (K~) + 256 (V~)
#define KSPLIT 4
#define KCHUNK (TDIM / KSPLIT)

// Scratch (static device globals; no allocation at runtime)
__device__ float g_part[KSPLIT * NROWS * EDIM];   // split-K partials
__device__ float g_Tt[NROWS * EDIM];              // reduced tildes
__device__ float g_Q[BDIM * HIDD * EDIM];
__device__ float g_K[BDIM * HIDD * EDIM];
__device__ float g_V[BDIM * HIDD * EDIM];
__device__ float g_A3[BDIM * 3 * EDIM];

// ---------------------------------------------------------------------------
// Stage 1: three skinny GEMMs  C[r][e] = sum_t A[r][t] * W[e][t]
//   mat0: Xp(192 x T) . Wq^T   -> rows [0,192)
//   mat1: Xc(256 x T) . Wk^T   -> rows [192,448)
//   mat2: Xc(256 x T) . Wv^T   -> rows [448,704)
// Tiling: 64x64 output tile, K blocked 16, split-K=4 into g_part.
// ---------------------------------------------------------------------------
__global__ __launch_bounds__(256) void stage1_gemm(
    const float* __restrict__ x, const float* __restrict__ Wq,
    const float* __restrict__ Wk, const float* __restrict__ Wv)
{
    int tile = blockIdx.x;   // 0..87  (3*8 + 4*8 + 4*8)
    int ks   = blockIdx.y;   // 0..KSPLIT-1
    int rpb, choff, matbase;
    const float* W;
    if (tile < 24)      { rpb = 3; choff = 0; matbase = 0;   W = Wq; }
    else if (tile < 56) { tile -= 24; rpb = 4; choff = 3; matbase = 192; W = Wk; }
    else                { tile -= 56; rpb = 4; choff = 3; matbase = 448; W = Wv; }
    int mtile = tile >> 3, ntile = tile & 7;
    int m0 = mtile * 64, n0 = ntile * 64, k0 = ks * KCHUNK;

    __shared__ float As[64][16];
    __shared__ float Bs[16][68];   // padded (68) -> conflict-free transposed store

    int tid = threadIdx.x;
    int lr  = tid >> 2;            // 0..63 : row within tile for the loads
    int kq  = (tid & 3) << 2;      // 0,4,8,12 : k quad

    int rg = m0 + lr;
    const float* arow = x + ((size_t)((rg / rpb) * 7 + choff + (rg % rpb))) * TDIM + k0 + kq;
    const float* brow = W + (size_t)(n0 + lr) * TDIM + k0 + kq;

    int tx = tid & 15, ty = tid >> 4;  // 16x16 thread grid, 4x4 microtile each

    float acc[4][4];
    #pragma unroll
    for (int i = 0; i < 4; i++)
        #pragma unroll
        for (int j = 0; j < 4; j++) acc[i][j] = 0.f;

    for (int kt = 0; kt < KCHUNK; kt += 16) {
        float4 av = *(const float4*)(arow + kt);
        float4 bv = *(const float4*)(brow + kt);
        __syncthreads();
        *(float4*)&As[lr][kq] = av;
        Bs[kq + 0][lr] = bv.x; Bs[kq + 1][lr] = bv.y;
        Bs[kq + 2][lr] = bv.z; Bs[kq + 3][lr] = bv.w;
        __syncthreads();
        #pragma unroll
        for (int k = 0; k < 16; k++) {
            float4 b4 = *(const float4*)&Bs[k][tx << 2];
            float a0 = As[(ty << 2) + 0][k];
            float a1 = As[(ty << 2) + 1][k];
            float a2 = As[(ty << 2) + 2][k];
            float a3 = As[(ty << 2) + 3][k];
            acc[0][0] += a0 * b4.x; acc[0][1] += a0 * b4.y; acc[0][2] += a0 * b4.z; acc[0][3] += a0 * b4.w;
            acc[1][0] += a1 * b4.x; acc[1][1] += a1 * b4.y; acc[1][2] += a1 * b4.z; acc[1][3] += a1 * b4.w;
            acc[2][0] += a2 * b4.x; acc[2][1] += a2 * b4.y; acc[2][2] += a2 * b4.z; acc[2][3] += a2 * b4.w;
            acc[3][0] += a3 * b4.x; acc[3][1] += a3 * b4.y; acc[3][2] += a3 * b4.z; acc[3][3] += a3 * b4.w;
        }
    }
    float* p = g_part + ((size_t)ks * NROWS + matbase + m0 + (ty << 2)) * EDIM + n0 + (tx << 2);
    #pragma unroll
    for (int i = 0; i < 4; i++)
        *(float4*)(p + (size_t)i * EDIM) = make_float4(acc[i][0], acc[i][1], acc[i][2], acc[i][3]);
}

__global__ void reduce_part()
{
    int i = blockIdx.x * 256 + threadIdx.x;
    if (i < NROWS * EDIM) {
        g_Tt[i] = g_part[i]
                + g_part[1 * NROWS * EDIM + i]
                + g_part[2 * NROWS * EDIM + i]
                + g_part[3 * NROWS * EDIM + i];
    }
}

// ---------------------------------------------------------------------------
// Stage 2a: Q = W1 . P~ + bq ; K = W2 . K~ + bk ; V = W2 . V~ + bv (per batch)
// ---------------------------------------------------------------------------
__global__ __launch_bounds__(256) void qkv_kernel(
    const float* __restrict__ W1, const float* __restrict__ W2,
    const float* __restrict__ bq, const float* __restrict__ bk,
    const float* __restrict__ bv)
{
    int b = blockIdx.x;
    __shared__ float w1s[HIDD * 3];
    __shared__ float w2s[HIDD * 4];
    int tid = threadIdx.x;
    if (tid < HIDD * 3) w1s[tid] = W1[tid];
    if (tid < HIDD * 4) w2s[tid] = W2[tid];
    __syncthreads();

    for (int e = tid; e < EDIM; e += 256) {
        float pt[3], kt[4], vt[4];
        #pragma unroll
        for (int c = 0; c < 3; c++) pt[c] = g_Tt[(b * 3 + c) * EDIM + e];
        #pragma unroll
        for (int c = 0; c < 4; c++) kt[c] = g_Tt[(192 + b * 4 + c) * EDIM + e];
        #pragma unroll
        for (int c = 0; c < 4; c++) vt[c] = g_Tt[(448 + b * 4 + c) * EDIM + e];
        float bqv = bq[e], bkv = bk[e], bvv = bv[e];
        #pragma unroll
        for (int o = 0; o < HIDD; o++) {
            float q = bqv, kk = bkv, vv = bvv;
            #pragma unroll
            for (int c = 0; c < 3; c++) q += w1s[o * 3 + c] * pt[c];
            #pragma unroll
            for (int c = 0; c < 4; c++) { kk += w2s[o * 4 + c] * kt[c]; vv += w2s[o * 4 + c] * vt[c]; }
            g_Q[((size_t)b * HIDD + o) * EDIM + e] = q;
            g_K[((size_t)b * HIDD + o) * EDIM + e] = kk;
            g_V[((size_t)b * HIDD + o) * EDIM + e] = vv;
        }
    }
}

// ---------------------------------------------------------------------------
// Stage 2b: per (b, 16-row e-tile):
//   S[e,f] = 0.25 * sum_c Q[c,e] K[c,f]; softmax over f;
//   attn[c,e] = sum_f w[e,f] V[c,f];  A3[o,e] = sum_c W3[o,c] attn[c,e]
// Never materializes attn/weights in HBM.
// ---------------------------------------------------------------------------
__global__ __launch_bounds__(256) void attn_kernel(const float* __restrict__ W3)
{
    int b = blockIdx.x, e0 = blockIdx.y * 16;
    __shared__ float KVs[HIDD * EDIM];   // 32 KB, reused K then V
    __shared__ float Qs[HIDD * 16];
    __shared__ float attn_s[HIDD * 16];

    int tid = threadIdx.x, lane = tid & 31, w = tid >> 5;

    {   // load K tile (coalesced float4)
        const float4* src = (const float4*)(g_K + (size_t)b * HIDD * EDIM);
        float4* dst = (float4*)KVs;
        for (int i = tid; i < HIDD * EDIM / 4; i += 256) dst[i] = src[i];
        int c = tid >> 4, r = tid & 15;
        Qs[c * 16 + r] = g_Q[((size_t)b * HIDD + c) * EDIM + e0 + r] * 0.25f;  // fold scale
    }
    __syncthreads();

    int r0 = w * 2, r1 = r0 + 1;
    float q0[HIDD], q1[HIDD];
    #pragma unroll
    for (int c = 0; c < HIDD; c++) { q0[c] = Qs[c * 16 + r0]; q1[c] = Qs[c * 16 + r1]; }

    float s0[16], s1[16];
    #pragma unroll
    for (int j = 0; j < 16; j++) {
        int f = lane + 32 * j;
        float a = 0.f, bb = 0.f;
        #pragma unroll
        for (int c = 0; c < HIDD; c++) {
            float kv = KVs[c * EDIM + f];
            a += q0[c] * kv; bb += q1[c] * kv;
        }
        s0[j] = a; s1[j] = bb;
    }

    // softmax over f for each of the two rows this warp owns
    #pragma unroll
    for (int rr = 0; rr < 2; rr++) {
        float* s = rr ? s1 : s0;
        float m = s[0];
        #pragma unroll
        for (int j = 1; j < 16; j++) m = fmaxf(m, s[j]);
        #pragma unroll
        for (int off = 16; off > 0; off >>= 1) m = fmaxf(m, __shfl_xor_sync(0xffffffffu, m, off));
        float sum = 0.f;
        #pragma unroll
        for (int j = 0; j < 16; j++) { s[j] = __expf(s[j] - m); sum += s[j]; }
        #pragma unroll
        for (int off = 16; off > 0; off >>= 1) sum += __shfl_xor_sync(0xffffffffu, sum, off);
        float inv = 1.f / sum;
        #pragma unroll
        for (int j = 0; j < 16; j++) s[j] *= inv;
    }

    __syncthreads();   // everyone done reading K
    {   // overwrite with V
        const float4* src = (const float4*)(g_V + (size_t)b * HIDD * EDIM);
        float4* dst = (float4*)KVs;
        for (int i = tid; i < HIDD * EDIM / 4; i += 256) dst[i] = src[i];
    }
    __syncthreads();

    float pa0[HIDD], pa1[HIDD];
    #pragma unroll
    for (int c = 0; c < HIDD; c++) { pa0[c] = 0.f; pa1[c] = 0.f; }
    #pragma unroll
    for (int j = 0; j < 16; j++) {
        int f = lane + 32 * j;
        float w0 = s0[j], w1 = s1[j];
        #pragma unroll
        for (int c = 0; c < HIDD; c++) {
            float vv = KVs[c * EDIM + f];
            pa0[c] += w0 * vv; pa1[c] += w1 * vv;
        }
    }
    #pragma unroll
    for (int off = 16; off > 0; off >>= 1) {
        #pragma unroll
        for (int c = 0; c < HIDD; c++) {
            pa0[c] += __shfl_xor_sync(0xffffffffu, pa0[c], off);
            pa1[c] += __shfl_xor_sync(0xffffffffu, pa1[c], off);
        }
    }
    if (lane == 0) {
        #pragma unroll
        for (int c = 0; c < HIDD; c++) {
            attn_s[c * 16 + r0] = pa0[c];
            attn_s[c * 16 + r1] = pa1[c];
        }
    }
    __syncthreads();

    if (tid < 48) {
        int o = tid >> 4, r = tid & 15;
        float a = 0.f;
        #pragma unroll
        for (int c = 0; c < HIDD; c++) a += W3[o * HIDD + c] * attn_s[c * 16 + r];
        g_A3[((size_t)b * 3 + o) * EDIM + e0 + r] = a;
    }
}

// ---------------------------------------------------------------------------
// Stage 3: out[b,o,t] = p[b,o,t] + sum_e A3[b,o,e] Wo[t,e] + rowsum(W3)[o]*bo[t]
// One thread per t; A3 rows broadcast from smem; Wo read exactly once.
// ---------------------------------------------------------------------------
__global__ __launch_bounds__(256) void final_kernel(
    const float* __restrict__ x, const float* __restrict__ Wo,
    const float* __restrict__ bo, const float* __restrict__ W3,
    float* __restrict__ out)
{
    int b = blockIdx.x;
    int tid = threadIdx.x;
    int t = blockIdx.y * 256 + tid;

    __shared__ float a3s[3 * EDIM];
    __shared__ float w3s[3];
    for (int i = tid; i < 3 * EDIM; i += 256) a3s[i] = g_A3[(size_t)b * 3 * EDIM + i];
    if (tid < 3) {
        float s = 0.f;
        #pragma unroll
        for (int c = 0; c < HIDD; c++) s += W3[tid * HIDD + c];
        w3s[tid] = s;
    }
    __syncthreads();

    const float4* wrow = (const float4*)(Wo + (size_t)t * EDIM);
    const float4* a0 = (const float4*)(a3s);
    const float4* a1 = (const float4*)(a3s + EDIM);
    const float4* a2 = (const float4*)(a3s + 2 * EDIM);

    float acc0 = 0.f, acc1 = 0.f, acc2 = 0.f;
    #pragma unroll 8
    for (int e = 0; e < EDIM / 4; e++) {
        float4 wv = wrow[e];
        float4 v0 = a0[e], v1 = a1[e], v2 = a2[e];
        acc0 += wv.x * v0.x + wv.y * v0.y + wv.z * v0.z + wv.w * v0.w;
        acc1 += wv.x * v1.x + wv.y * v1.y + wv.z * v1.z + wv.w * v1.w;
        acc2 += wv.x * v2.x + wv.y * v2.y + wv.z * v2.z + wv.w * v2.w;
    }
    float bov = bo[t];
    out[((size_t)b * 3 + 0) * TDIM + t] = x[((size_t)b * 7 + 0) * TDIM + t] + acc0 + w3s[0] * bov;
    out[((size_t)b * 3 + 1) * TDIM + t] = x[((size_t)b * 7 + 1) * TDIM + t] + acc1 + w3s[1] * bov;
    out[((size_t)b * 3 + 2) * TDIM + t] = x[((size_t)b * 7 + 2) * TDIM + t] + acc2 + w3s[2] * bov;
}

// ---------------------------------------------------------------------------
extern "C" void kernel_launch(void* const* d_in, const int* in_sizes, int n_in,
                              void* d_out, int out_size)
{
    const float* x  = (const float*)d_in[0];
    const float* W1 = (const float*)d_in[1];
    const float* W2 = (const float*)d_in[2];
    const float* Wq = (const float*)d_in[3];
    const float* bq = (const float*)d_in[4];
    const float* Wk = (const float*)d_in[5];
    const float* bk = (const float*)d_in[6];
    const float* Wv = (const float*)d_in[7];
    const float* bv = (const float*)d_in[8];
    const float* Wo = (const float*)d_in[9];
    const float* bo = (const float*)d_in[10];
    const float* W3 = (const float*)d_in[11];
    float* out = (float*)d_out;

    stage1_gemm<<<dim3(88, KSPLIT), 256>>>(x, Wq, Wk, Wv);
    reduce_part<<<(NROWS * EDIM + 255) / 256, 256>>>();
    qkv_kernel<<<BDIM, 256>>>(W1, W2, bq, bk, bv);
    attn_kernel<<<dim3(BDIM, EDIM / 16), 256>>>(W3);
    final_kernel<<<dim3(BDIM, TDIM / 256), 256>>>(x, Wo, bo, W3, out);
}

// round 3
// speedup vs baseline: 1.8935x; 1.8935x over previous
#include <cuda_runtime.h>
#include <math.h>

#define TDIM 16384
#define BDIM 64
#define EDIM 512
#define HIDD 16
#define NROWS 704            // 192 (P~) + 256 (K~) + 256 (V~)
#define KS 8
#define KCH (TDIM / KS)      // 2048

// Scratch (static device globals; no allocation at runtime)
__device__ float g_part[KS * NROWS * EDIM];       // split-K partials (11.5 MB)
__device__ float g_Tt[NROWS * EDIM];              // reduced tildes
__device__ float g_Q[BDIM * HIDD * EDIM];
__device__ float g_K[BDIM * HIDD * EDIM];
__device__ float g_V[BDIM * HIDD * EDIM];
__device__ float g_A3[BDIM * 3 * EDIM];

// ---------------------------------------------------------------------------
// Stage 1: C[r][e] = sum_t A[r][t] * W[e][t]  for the 704-row stacked operand
//   rows [0,192)  : Xp . Wq^T
//   rows [192,448): Xc . Wk^T
//   rows [448,704): Xc . Wv^T
// 64x64 tiles, K split 8 ways, double-buffered smem, transposed tiles so the
// inner loop is 2x LDS.128 + 16 FFMA per k (FFMA-pipe bound).
// ---------------------------------------------------------------------------
#define SSTRIDE 68

__global__ __launch_bounds__(256) void stage1_gemm(
    const float* __restrict__ x, const float* __restrict__ Wq,
    const float* __restrict__ Wk, const float* __restrict__ Wv)
{
    int tile = blockIdx.x;               // 0..87
    int ks   = blockIdx.y;               // 0..KS-1
    int mtile = tile >> 3, ntile = tile & 7;
    int m0 = mtile * 64, n0 = ntile * 64, k0 = ks * KCH;
    const float* W = (mtile < 3) ? Wq : (mtile < 7 ? Wk : Wv);

    __shared__ float As[2][16][SSTRIDE];   // [k][m], transposed
    __shared__ float Bs[2][16][SSTRIDE];   // [k][n], transposed

    int tid = threadIdx.x;
    int lr  = tid >> 2;                    // 0..63 : row within tile (loads)
    int kq  = (tid & 3) << 2;              // 0,4,8,12 : k quad

    int r = m0 + lr;
    int xrow;
    if (r < 192) xrow = (r / 3) * 7 + (r % 3);
    else { int rr = (r - 192) & 255; xrow = (rr >> 2) * 7 + 3 + (rr & 3); }
    const float* arow = x + (size_t)xrow * TDIM + k0 + kq;
    const float* brow = W + (size_t)(n0 + lr) * TDIM + k0 + kq;

    int tx = tid & 15, ty = tid >> 4;      // 16x16 grid, 4x4 microtile
    int mm = ty << 2, nn = tx << 2;

    float acc[4][4];
    #pragma unroll
    for (int i = 0; i < 4; i++)
        #pragma unroll
        for (int j = 0; j < 4; j++) acc[i][j] = 0.f;

    // prefetch iter 0 and fill buffer 0
    float4 av = *(const float4*)arow;
    float4 bv = *(const float4*)brow;
    As[0][kq + 0][lr] = av.x; As[0][kq + 1][lr] = av.y;
    As[0][kq + 2][lr] = av.z; As[0][kq + 3][lr] = av.w;
    Bs[0][kq + 0][lr] = bv.x; Bs[0][kq + 1][lr] = bv.y;
    Bs[0][kq + 2][lr] = bv.z; Bs[0][kq + 3][lr] = bv.w;
    __syncthreads();

    const int nIter = KCH / 16;            // 128
    for (int it = 0; it < nIter; it++) {
        int cur = it & 1, nxt = cur ^ 1;
        float4 a2, b2;
        bool more = (it + 1 < nIter);
        if (more) {
            a2 = *(const float4*)(arow + (it + 1) * 16);
            b2 = *(const float4*)(brow + (it + 1) * 16);
        }
        const float (*Ac)[SSTRIDE] = As[cur];
        const float (*Bc)[SSTRIDE] = Bs[cur];
        #pragma unroll
        for (int k = 0; k < 16; k++) {
            float4 a4 = *(const float4*)&Ac[k][mm];
            float4 b4 = *(const float4*)&Bc[k][nn];
            acc[0][0] += a4.x * b4.x; acc[0][1] += a4.x * b4.y; acc[0][2] += a4.x * b4.z; acc[0][3] += a4.x * b4.w;
            acc[1][0] += a4.y * b4.x; acc[1][1] += a4.y * b4.y; acc[1][2] += a4.y * b4.z; acc[1][3] += a4.y * b4.w;
            acc[2][0] += a4.z * b4.x; acc[2][1] += a4.z * b4.y; acc[2][2] += a4.z * b4.z; acc[2][3] += a4.z * b4.w;
            acc[3][0] += a4.w * b4.x; acc[3][1] += a4.w * b4.y; acc[3][2] += a4.w * b4.z; acc[3][3] += a4.w * b4.w;
        }
        if (more) {
            As[nxt][kq + 0][lr] = a2.x; As[nxt][kq + 1][lr] = a2.y;
            As[nxt][kq + 2][lr] = a2.z; As[nxt][kq + 3][lr] = a2.w;
            Bs[nxt][kq + 0][lr] = b2.x; Bs[nxt][kq + 1][lr] = b2.y;
            Bs[nxt][kq + 2][lr] = b2.z; Bs[nxt][kq + 3][lr] = b2.w;
        }
        __syncthreads();
    }

    float* p = g_part + ((size_t)ks * NROWS + m0 + mm) * EDIM + n0 + nn;
    #pragma unroll
    for (int i = 0; i < 4; i++)
        *(float4*)(p + (size_t)i * EDIM) = make_float4(acc[i][0], acc[i][1], acc[i][2], acc[i][3]);
}

__global__ void reduce_part()
{
    int i = blockIdx.x * 256 + threadIdx.x;
    if (i < NROWS * EDIM) {
        float s = 0.f;
        #pragma unroll
        for (int k = 0; k < KS; k++) s += g_part[(size_t)k * NROWS * EDIM + i];
        g_Tt[i] = s;
    }
}

// ---------------------------------------------------------------------------
// Stage 2a: Q = W1 . P~ + bq ; K = W2 . K~ + bk ; V = W2 . V~ + bv (per batch)
// ---------------------------------------------------------------------------
__global__ __launch_bounds__(256) void qkv_kernel(
    const float* __restrict__ W1, const float* __restrict__ W2,
    const float* __restrict__ bq, const float* __restrict__ bk,
    const float* __restrict__ bv)
{
    int b = blockIdx.x;
    __shared__ float w1s[HIDD * 3];
    __shared__ float w2s[HIDD * 4];
    int tid = threadIdx.x;
    if (tid < HIDD * 3) w1s[tid] = W1[tid];
    if (tid < HIDD * 4) w2s[tid] = W2[tid];
    __syncthreads();

    for (int e = tid; e < EDIM; e += 256) {
        float pt[3], kt[4], vt[4];
        #pragma unroll
        for (int c = 0; c < 3; c++) pt[c] = g_Tt[(b * 3 + c) * EDIM + e];
        #pragma unroll
        for (int c = 0; c < 4; c++) kt[c] = g_Tt[(192 + b * 4 + c) * EDIM + e];
        #pragma unroll
        for (int c = 0; c < 4; c++) vt[c] = g_Tt[(448 + b * 4 + c) * EDIM + e];
        float bqv = bq[e], bkv = bk[e], bvv = bv[e];
        #pragma unroll
        for (int o = 0; o < HIDD; o++) {
            float q = bqv, kk = bkv, vv = bvv;
            #pragma unroll
            for (int c = 0; c < 3; c++) q += w1s[o * 3 + c] * pt[c];
            #pragma unroll
            for (int c = 0; c < 4; c++) { kk += w2s[o * 4 + c] * kt[c]; vv += w2s[o * 4 + c] * vt[c]; }
            g_Q[((size_t)b * HIDD + o) * EDIM + e] = q;
            g_K[((size_t)b * HIDD + o) * EDIM + e] = kk;
            g_V[((size_t)b * HIDD + o) * EDIM + e] = vv;
        }
    }
}

// ---------------------------------------------------------------------------
// Stage 2b: per (b, 16-row e-tile):
//   S[e,f] = 0.25 * sum_c Q[c,e] K[c,f]; softmax over f;
//   attn[c,e] = sum_f w[e,f] V[c,f];  A3[o,e] = sum_c W3[o,c] attn[c,e]
// ---------------------------------------------------------------------------
__global__ __launch_bounds__(256) void attn_kernel(const float* __restrict__ W3)
{
    int b = blockIdx.x, e0 = blockIdx.y * 16;
    __shared__ float KVs[HIDD * EDIM];   // 32 KB, reused K then V
    __shared__ float Qs[HIDD * 16];
    __shared__ float attn_s[HIDD * 16];

    int tid = threadIdx.x, lane = tid & 31, w = tid >> 5;

    {   // load K tile (coalesced float4)
        const float4* src = (const float4*)(g_K + (size_t)b * HIDD * EDIM);
        float4* dst = (float4*)KVs;
        for (int i = tid; i < HIDD * EDIM / 4; i += 256) dst[i] = src[i];
        int c = tid >> 4, r = tid & 15;
        Qs[c * 16 + r] = g_Q[((size_t)b * HIDD + c) * EDIM + e0 + r] * 0.25f;  // fold scale
    }
    __syncthreads();

    int r0 = w * 2, r1 = r0 + 1;
    float q0[HIDD], q1[HIDD];
    #pragma unroll
    for (int c = 0; c < HIDD; c++) { q0[c] = Qs[c * 16 + r0]; q1[c] = Qs[c * 16 + r1]; }

    float s0[16], s1[16];
    #pragma unroll
    for (int j = 0; j < 16; j++) {
        int f = lane + 32 * j;
        float a = 0.f, bb = 0.f;
        #pragma unroll
        for (int c = 0; c < HIDD; c++) {
            float kv = KVs[c * EDIM + f];
            a += q0[c] * kv; bb += q1[c] * kv;
        }
        s0[j] = a; s1[j] = bb;
    }

    #pragma unroll
    for (int rr = 0; rr < 2; rr++) {
        float* s = rr ? s1 : s0;
        float m = s[0];
        #pragma unroll
        for (int j = 1; j < 16; j++) m = fmaxf(m, s[j]);
        #pragma unroll
        for (int off = 16; off > 0; off >>= 1) m = fmaxf(m, __shfl_xor_sync(0xffffffffu, m, off));
        float sum = 0.f;
        #pragma unroll
        for (int j = 0; j < 16; j++) { s[j] = __expf(s[j] - m); sum += s[j]; }
        #pragma unroll
        for (int off = 16; off > 0; off >>= 1) sum += __shfl_xor_sync(0xffffffffu, sum, off);
        float inv = 1.f / sum;
        #pragma unroll
        for (int j = 0; j < 16; j++) s[j] *= inv;
    }

    __syncthreads();   // everyone done reading K
    {   // overwrite with V
        const float4* src = (const float4*)(g_V + (size_t)b * HIDD * EDIM);
        float4* dst = (float4*)KVs;
        for (int i = tid; i < HIDD * EDIM / 4; i += 256) dst[i] = src[i];
    }
    __syncthreads();

    float pa0[HIDD], pa1[HIDD];
    #pragma unroll
    for (int c = 0; c < HIDD; c++) { pa0[c] = 0.f; pa1[c] = 0.f; }
    #pragma unroll
    for (int j = 0; j < 16; j++) {
        int f = lane + 32 * j;
        float w0 = s0[j], w1 = s1[j];
        #pragma unroll
        for (int c = 0; c < HIDD; c++) {
            float vv = KVs[c * EDIM + f];
            pa0[c] += w0 * vv; pa1[c] += w1 * vv;
        }
    }
    #pragma unroll
    for (int off = 16; off > 0; off >>= 1) {
        #pragma unroll
        for (int c = 0; c < HIDD; c++) {
            pa0[c] += __shfl_xor_sync(0xffffffffu, pa0[c], off);
            pa1[c] += __shfl_xor_sync(0xffffffffu, pa1[c], off);
        }
    }
    if (lane == 0) {
        #pragma unroll
        for (int c = 0; c < HIDD; c++) {
            attn_s[c * 16 + r0] = pa0[c];
            attn_s[c * 16 + r1] = pa1[c];
        }
    }
    __syncthreads();

    if (tid < 48) {
        int o = tid >> 4, r = tid & 15;
        float a = 0.f;
        #pragma unroll
        for (int c = 0; c < HIDD; c++) a += W3[o * HIDD + c] * attn_s[c * 16 + r];
        g_A3[((size_t)b * 3 + o) * EDIM + e0 + r] = a;
    }
}

// ---------------------------------------------------------------------------
// Stage 3: out[b,o,t] = p[b,o,t] + sum_e A3[b,o,e] Wo[t,e] + rowsum(W3)[o]*bo[t]
// Two t-values per thread: 24 FFMA per 5 loads.
// ---------------------------------------------------------------------------
__global__ __launch_bounds__(256) void final_kernel(
    const float* __restrict__ x, const float* __restrict__ Wo,
    const float* __restrict__ bo, const float* __restrict__ W3,
    float* __restrict__ out)
{
    int b = blockIdx.x;
    int tid = threadIdx.x;
    int ta = blockIdx.y * 512 + tid;
    int tb = ta + 256;

    __shared__ float a3s[3 * EDIM];
    __shared__ float w3s[3];
    for (int i = tid; i < 3 * EDIM; i += 256) a3s[i] = g_A3[(size_t)b * 3 * EDIM + i];
    if (tid < 3) {
        float s = 0.f;
        #pragma unroll
        for (int c = 0; c < HIDD; c++) s += W3[tid * HIDD + c];
        w3s[tid] = s;
    }
    __syncthreads();

    const float4* wra = (const float4*)(Wo + (size_t)ta * EDIM);
    const float4* wrb = (const float4*)(Wo + (size_t)tb * EDIM);
    const float4* a0 = (const float4*)(a3s);
    const float4* a1 = (const float4*)(a3s + EDIM);
    const float4* a2 = (const float4*)(a3s + 2 * EDIM);

    float a00 = 0.f, a01 = 0.f, a02 = 0.f;
    float a10 = 0.f, a11 = 0.f, a12 = 0.f;
    #pragma unroll 4
    for (int e = 0; e < EDIM / 4; e++) {
        float4 wa = wra[e];
        float4 wb = wrb[e];
        float4 v0 = a0[e], v1 = a1[e], v2 = a2[e];
        a00 += wa.x * v0.x + wa.y * v0.y + wa.z * v0.z + wa.w * v0.w;
        a01 += wa.x * v1.x + wa.y * v1.y + wa.z * v1.z + wa.w * v1.w;
        a02 += wa.x * v2.x + wa.y * v2.y + wa.z * v2.z + wa.w * v2.w;
        a10 += wb.x * v0.x + wb.y * v0.y + wb.z * v0.z + wb.w * v0.w;
        a11 += wb.x * v1.x + wb.y * v1.y + wb.z * v1.z + wb.w * v1.w;
        a12 += wb.x * v2.x + wb.y * v2.y + wb.z * v2.z + wb.w * v2.w;
    }
    float boa = bo[ta], bob = bo[tb];
    out[((size_t)b * 3 + 0) * TDIM + ta] = x[((size_t)b * 7 + 0) * TDIM + ta] + a00 + w3s[0] * boa;
    out[((size_t)b * 3 + 1) * TDIM + ta] = x[((size_t)b * 7 + 1) * TDIM + ta] + a01 + w3s[1] * boa;
    out[((size_t)b * 3 + 2) * TDIM + ta] = x[((size_t)b * 7 + 2) * TDIM + ta] + a02 + w3s[2] * boa;
    out[((size_t)b * 3 + 0) * TDIM + tb] = x[((size_t)b * 7 + 0) * TDIM + tb] + a10 + w3s[0] * bob;
    out[((size_t)b * 3 + 1) * TDIM + tb] = x[((size_t)b * 7 + 1) * TDIM + tb] + a11 + w3s[1] * bob;
    out[((size_t)b * 3 + 2) * TDIM + tb] = x[((size_t)b * 7 + 2) * TDIM + tb] + a12 + w3s[2] * bob;
}

// ---------------------------------------------------------------------------
extern "C" void kernel_launch(void* const* d_in, const int* in_sizes, int n_in,
                              void* d_out, int out_size)
{
    const float* x  = (const float*)d_in[0];
    const float* W1 = (const float*)d_in[1];
    const float* W2 = (const float*)d_in[2];
    const float* Wq = (const float*)d_in[3];
    const float* bq = (const float*)d_in[4];
    const float* Wk = (const float*)d_in[5];
    const float* bk = (const float*)d_in[6];
    const float* Wv = (const float*)d_in[7];
    const float* bv = (const float*)d_in[8];
    const float* Wo = (const float*)d_in[9];
    const float* bo = (const float*)d_in[10];
    const float* W3 = (const float*)d_in[11];
    float* out = (float*)d_out;

    stage1_gemm<<<dim3(88, KS), 256>>>(x, Wq, Wk, Wv);
    reduce_part<<<(NROWS * EDIM + 255) / 256, 256>>>();
    qkv_kernel<<<BDIM, 256>>>(W1, W2, bq, bk, bv);
    attn_kernel<<<dim3(BDIM, EDIM / 16), 256>>>(W3);
    final_kernel<<<dim3(BDIM, TDIM / 512), 256>>>(x, Wo, bo, W3, out);
}

// round 5
// speedup vs baseline: 2.4539x; 1.2960x over previous
#include <cuda_runtime.h>
#include <cuda_bf16.h>
#include <math.h>

#define TDIM 16384
#define BDIM 64
#define EDIM 512
#define HIDD 16
#define NROWS 704            // compact: 192 (P~) + 256 (K~) + 256 (V~)
#define PROWS 768            // padded : 256 + 256 + 256
#define KS 6                 // split-K ways for stage1

// Scratch (static device globals; no allocation at runtime)
__device__ float g_part[KS * PROWS * EDIM];       // split-K partials (9.4 MB)
__device__ float g_Tt[NROWS * EDIM];              // reduced tildes (compact)
__device__ float g_Q[BDIM * HIDD * EDIM];
__device__ float g_K[BDIM * HIDD * EDIM];
__device__ float g_V[BDIM * HIDD * EDIM];
__device__ float g_A3[BDIM * 3 * EDIM];

// ---------------------------------------------------------------------------
// MMA / ldmatrix helpers (bf16 m16n8k16, fp32 accum)
// ---------------------------------------------------------------------------
__device__ __forceinline__ void ldmx4(unsigned &r0, unsigned &r1, unsigned &r2,
                                      unsigned &r3, unsigned addr) {
    asm volatile("ldmatrix.sync.aligned.m8n8.x4.shared.b16 {%0,%1,%2,%3}, [%4];"
                 : "=r"(r0), "=r"(r1), "=r"(r2), "=r"(r3) : "r"(addr));
}
__device__ __forceinline__ void ldmx2(unsigned &r0, unsigned &r1, unsigned addr) {
    asm volatile("ldmatrix.sync.aligned.m8n8.x2.shared.b16 {%0,%1}, [%2];"
                 : "=r"(r0), "=r"(r1) : "r"(addr));
}
__device__ __forceinline__ void mma16816(float *c, const unsigned *a, const unsigned *b) {
    asm volatile(
        "mma.sync.aligned.m16n8k16.row.col.f32.bf16.bf16.f32 "
        "{%0,%1,%2,%3}, {%4,%5,%6,%7}, {%8,%9}, {%0,%1,%2,%3};"
        : "+f"(c[0]), "+f"(c[1]), "+f"(c[2]), "+f"(c[3])
        : "r"(a[0]), "r"(a[1]), "r"(a[2]), "r"(a[3]), "r"(b[0]), "r"(b[1]));
}

// convert 8 consecutive fp32 -> 8 bf16 hi + 8 bf16 lo, packed for STS.128
__device__ __forceinline__ void cvt8(const float *f, uint4 &hi, uint4 &lo) {
    unsigned hs[8], ls[8];
    #pragma unroll
    for (int i = 0; i < 8; i++) {
        __nv_bfloat16 h = __float2bfloat16(f[i]);
        float hf = __bfloat162float(h);
        __nv_bfloat16 l = __float2bfloat16(f[i] - hf);
        hs[i] = (unsigned)reinterpret_cast<unsigned short &>(h);
        ls[i] = (unsigned)reinterpret_cast<unsigned short &>(l);
    }
    hi.x = hs[0] | (hs[1] << 16); hi.y = hs[2] | (hs[3] << 16);
    hi.z = hs[4] | (hs[5] << 16); hi.w = hs[6] | (hs[7] << 16);
    lo.x = ls[0] | (ls[1] << 16); lo.y = ls[2] | (ls[3] << 16);
    lo.z = ls[4] | (ls[5] << 16); lo.w = ls[6] | (ls[7] << 16);
}

// ---------------------------------------------------------------------------
// Stage 1 (tensor): C[r][e] = sum_t A[r][t] * W[e][t], padded-stacked rows.
//   padded rows [0,256)   : Xp (192 valid) . Wq^T
//   padded rows [256,512) : Xc . Wk^T
//   padded rows [512,768) : Xc . Wv^T
// CTA: 128x128 tile, 512 threads (4x4 warps of 32x32), k-step 32,
// double-buffered bf16 hi/lo smem tiles, bf16-split 3-term MMA.
// ---------------------------------------------------------------------------
#define LDB 40                         // bf16 row stride (80 B) - conflict-free ldmatrix
#define TILEB (128 * LDB)              // ush elements per buffer per tile
#define SMEM_S1 (4 * 2 * TILEB * 2)    // bytes: Ah,Al,Bh,Bl x 2 buffers x 2B

__global__ __launch_bounds__(512, 1) void stage1_mma(
    const float* __restrict__ x, const float* __restrict__ Wq,
    const float* __restrict__ Wk, const float* __restrict__ Wv)
{
    extern __shared__ unsigned short dynsm[];
    unsigned short* Ah = dynsm;
    unsigned short* Al = Ah + 2 * TILEB;
    unsigned short* Bh = Al + 2 * TILEB;
    unsigned short* Bl = Bh + 2 * TILEB;

    int mt = blockIdx.x >> 2;          // 0..5
    int nt = blockIdx.x & 3;           // 0..3
    int ks = blockIdx.y;               // 0..5
    int k0 = ks * 2752;
    int len = (ks < 5) ? 2752 : 2624;
    int nIter = len >> 5;              // k-steps of 32

    const float* W = (mt < 2) ? Wq : (mt < 4 ? Wk : Wv);

    int tid  = threadIdx.x;
    int lane = tid & 31;
    int wid  = tid >> 5;               // 0..15
    int wm   = wid >> 2;               // warp m 0..3 (32 rows each)
    int wn   = wid & 3;                // warp n 0..3 (32 cols each)

    // ---- global load mapping: each thread owns (row, 8-k-slice) ----
    int lrow = tid >> 2;               // 0..127
    int kq8  = (tid & 3) << 3;         // 0,8,16,24

    int pr = mt * 128 + lrow;          // padded stacked row
    int mat = pr >> 8, loc = pr & 255;
    int xrow;
    if (mat == 0) xrow = (loc < 192) ? ((loc / 3) * 7 + (loc % 3)) : 0;
    else          xrow = (loc >> 2) * 7 + 3 + (loc & 3);
    const float* pA = x + (size_t)xrow * TDIM + k0 + kq8;
    const float* pB = W + (size_t)(nt * 128 + lrow) * TDIM + k0 + kq8;

    int sidx = TILEB * 0 + lrow * LDB + kq8;   // within-buffer ush index

    float acc[2][4][4];
    #pragma unroll
    for (int mi = 0; mi < 2; mi++)
        #pragma unroll
        for (int ni = 0; ni < 4; ni++)
            #pragma unroll
            for (int r = 0; r < 4; r++) acc[mi][ni][r] = 0.f;

    // ---- preload iter 0 ----
    float fa[8], fb[8];
    *(float4*)&fa[0] = *(const float4*)pA;  *(float4*)&fa[4] = *(const float4*)(pA + 4);
    *(float4*)&fb[0] = *(const float4*)pB;  *(float4*)&fb[4] = *(const float4*)(pB + 4);
    {
        uint4 hi, lo;
        cvt8(fa, hi, lo);
        *(uint4*)&Ah[sidx] = hi; *(uint4*)&Al[sidx] = lo;
        cvt8(fb, hi, lo);
        *(uint4*)&Bh[sidx] = hi; *(uint4*)&Bl[sidx] = lo;
    }
    __syncthreads();

    // smem base addresses (shared-state-space u32) for ldmatrix
    unsigned baseAh = (unsigned)__cvta_generic_to_shared(Ah);
    unsigned baseAl = (unsigned)__cvta_generic_to_shared(Al);
    unsigned baseBh = (unsigned)__cvta_generic_to_shared(Bh);
    unsigned baseBl = (unsigned)__cvta_generic_to_shared(Bl);

    // per-lane ldmatrix row/col offsets
    int aRow = wm * 32 + (lane & 15);            // + mi*16
    int aCol = (lane >> 4) << 3;                 // + k16
    int bRow = wn * 32 + (lane & 7);             // + ni*8
    int bCol = ((lane >> 3) & 1) << 3;           // + k16

    for (int it = 0; it < nIter; it++) {
        int buf = it & 1;
        bool more = (it + 1 < nIter);
        if (more) {
            const float* qA = pA + (it + 1) * 32;
            const float* qB = pB + (it + 1) * 32;
            *(float4*)&fa[0] = *(const float4*)qA;  *(float4*)&fa[4] = *(const float4*)(qA + 4);
            *(float4*)&fb[0] = *(const float4*)qB;  *(float4*)&fb[4] = *(const float4*)(qB + 4);
        }

        unsigned bufOff = (unsigned)(buf * TILEB * 2);  // bytes
        #pragma unroll
        for (int kk = 0; kk < 2; kk++) {
            int k16 = kk << 4;
            unsigned bh[4][2], bl[4][2];
            #pragma unroll
            for (int ni = 0; ni < 4; ni++) {
                unsigned off = bufOff + (unsigned)((bRow + ni * 8) * LDB + (bCol + k16)) * 2u;
                ldmx2(bh[ni][0], bh[ni][1], baseBh + off);
                ldmx2(bl[ni][0], bl[ni][1], baseBl + off);
            }
            #pragma unroll
            for (int mi = 0; mi < 2; mi++) {
                unsigned off = bufOff + (unsigned)((aRow + mi * 16) * LDB + (aCol + k16)) * 2u;
                unsigned ah[4], al[4];
                ldmx4(ah[0], ah[1], ah[2], ah[3], baseAh + off);
                ldmx4(al[0], al[1], al[2], al[3], baseAl + off);
                #pragma unroll
                for (int ni = 0; ni < 4; ni++) {
                    mma16816(acc[mi][ni], ah, bh[ni]);
                    mma16816(acc[mi][ni], ah, bl[ni]);
                    mma16816(acc[mi][ni], al, bh[ni]);
                }
            }
        }

        if (more) {
            int d = ((buf ^ 1) * TILEB) + lrow * LDB + kq8;
            uint4 hi, lo;
            cvt8(fa, hi, lo);
            *(uint4*)&Ah[d] = hi; *(uint4*)&Al[d] = lo;
            cvt8(fb, hi, lo);
            *(uint4*)&Bh[d] = hi; *(uint4*)&Bl[d] = lo;
        }
        __syncthreads();
    }

    // ---- store accumulators to padded split-K scratch ----
    float* base = g_part + ((size_t)ks * PROWS + mt * 128 + wm * 32) * EDIM
                + nt * 128 + wn * 32;
    int rr = lane >> 2, cc = (lane & 3) << 1;
    #pragma unroll
    for (int mi = 0; mi < 2; mi++)
        #pragma unroll
        for (int ni = 0; ni < 4; ni++) {
            float* p0 = base + (size_t)(mi * 16 + rr) * EDIM + ni * 8 + cc;
            *(float2*)p0                    = make_float2(acc[mi][ni][0], acc[mi][ni][1]);
            *(float2*)(p0 + 8 * EDIM)       = make_float2(acc[mi][ni][2], acc[mi][ni][3]);
        }
}

// ---------------------------------------------------------------------------
__global__ void reduce_part()
{
    int i = blockIdx.x * 256 + threadIdx.x;
    if (i < NROWS * EDIM) {
        int r = i >> 9, e = i & 511;
        int pr = (r < 192) ? r : (r + 64);       // compact -> padded row
        size_t pi = (size_t)pr * EDIM + e;
        float s = 0.f;
        #pragma unroll
        for (int k = 0; k < KS; k++) s += g_part[(size_t)k * PROWS * EDIM + pi];
        g_Tt[i] = s;
    }
}

// ---------------------------------------------------------------------------
// Stage 2a: Q = W1 . P~ + bq ; K = W2 . K~ + bk ; V = W2 . V~ + bv (per batch)
// ---------------------------------------------------------------------------
__global__ __launch_bounds__(256) void qkv_kernel(
    const float* __restrict__ W1, const float* __restrict__ W2,
    const float* __restrict__ bq, const float* __restrict__ bk,
    const float* __restrict__ bv)
{
    int b = blockIdx.x;
    __shared__ float w1s[HIDD * 3];
    __shared__ float w2s[HIDD * 4];
    int tid = threadIdx.x;
    if (tid < HIDD * 3) w1s[tid] = W1[tid];
    if (tid < HIDD * 4) w2s[tid] = W2[tid];
    __syncthreads();

    for (int e = tid; e < EDIM; e += 256) {
        float pt[3], kt[4], vt[4];
        #pragma unroll
        for (int c = 0; c < 3; c++) pt[c] = g_Tt[(b * 3 + c) * EDIM + e];
        #pragma unroll
        for (int c = 0; c < 4; c++) kt[c] = g_Tt[(192 + b * 4 + c) * EDIM + e];
        #pragma unroll
        for (int c = 0; c < 4; c++) vt[c] = g_Tt[(448 + b * 4 + c) * EDIM + e];
        float bqv = bq[e], bkv = bk[e], bvv = bv[e];
        #pragma unroll
        for (int o = 0; o < HIDD; o++) {
            float q = bqv, kk = bkv, vv = bvv;
            #pragma unroll
            for (int c = 0; c < 3; c++) q += w1s[o * 3 + c] * pt[c];
            #pragma unroll
            for (int c = 0; c < 4; c++) { kk += w2s[o * 4 + c] * kt[c]; vv += w2s[o * 4 + c] * vt[c]; }
            g_Q[((size_t)b * HIDD + o) * EDIM + e] = q;
            g_K[((size_t)b * HIDD + o) * EDIM + e] = kk;
            g_V[((size_t)b * HIDD + o) * EDIM + e] = vv;
        }
    }
}

// ---------------------------------------------------------------------------
// Stage 2b: per (b, 16-row e-tile): softmax attention, fused W3 projection.
// ---------------------------------------------------------------------------
__global__ __launch_bounds__(256) void attn_kernel(const float* __restrict__ W3)
{
    int b = blockIdx.x, e0 = blockIdx.y * 16;
    __shared__ float KVs[HIDD * EDIM];   // 32 KB, reused K then V
    __shared__ float Qs[HIDD * 16];
    __shared__ float attn_s[HIDD * 16];

    int tid = threadIdx.x, lane = tid & 31, w = tid >> 5;

    {
        const float4* src = (const float4*)(g_K + (size_t)b * HIDD * EDIM);
        float4* dst = (float4*)KVs;
        for (int i = tid; i < HIDD * EDIM / 4; i += 256) dst[i] = src[i];
        int c = tid >> 4, r = tid & 15;
        Qs[c * 16 + r] = g_Q[((size_t)b * HIDD + c) * EDIM + e0 + r] * 0.25f;
    }
    __syncthreads();

    int r0 = w * 2, r1 = r0 + 1;
    float q0[HIDD], q1[HIDD];
    #pragma unroll
    for (int c = 0; c < HIDD; c++) { q0[c] = Qs[c * 16 + r0]; q1[c] = Qs[c * 16 + r1]; }

    float s0[16], s1[16];
    #pragma unroll
    for (int j = 0; j < 16; j++) {
        int f = lane + 32 * j;
        float a = 0.f, bb = 0.f;
        #pragma unroll
        for (int c = 0; c < HIDD; c++) {
            float kv = KVs[c * EDIM + f];
            a += q0[c] * kv; bb += q1[c] * kv;
        }
        s0[j] = a; s1[j] = bb;
    }

    #pragma unroll
    for (int rr = 0; rr < 2; rr++) {
        float* s = rr ? s1 : s0;
        float m = s[0];
        #pragma unroll
        for (int j = 1; j < 16; j++) m = fmaxf(m, s[j]);
        #pragma unroll
        for (int off = 16; off > 0; off >>= 1) m = fmaxf(m, __shfl_xor_sync(0xffffffffu, m, off));
        float sum = 0.f;
        #pragma unroll
        for (int j = 0; j < 16; j++) { s[j] = __expf(s[j] - m); sum += s[j]; }
        #pragma unroll
        for (int off = 16; off > 0; off >>= 1) sum += __shfl_xor_sync(0xffffffffu, sum, off);
        float inv = 1.f / sum;
        #pragma unroll
        for (int j = 0; j < 16; j++) s[j] *= inv;
    }

    __syncthreads();
    {
        const float4* src = (const float4*)(g_V + (size_t)b * HIDD * EDIM);
        float4* dst = (float4*)KVs;
        for (int i = tid; i < HIDD * EDIM / 4; i += 256) dst[i] = src[i];
    }
    __syncthreads();

    float pa0[HIDD], pa1[HIDD];
    #pragma unroll
    for (int c = 0; c < HIDD; c++) { pa0[c] = 0.f; pa1[c] = 0.f; }
    #pragma unroll
    for (int j = 0; j < 16; j++) {
        int f = lane + 32 * j;
        float w0 = s0[j], w1 = s1[j];
        #pragma unroll
        for (int c = 0; c < HIDD; c++) {
            float vv = KVs[c * EDIM + f];
            pa0[c] += w0 * vv; pa1[c] += w1 * vv;
        }
    }
    #pragma unroll
    for (int off = 16; off > 0; off >>= 1) {
        #pragma unroll
        for (int c = 0; c < HIDD; c++) {
            pa0[c] += __shfl_xor_sync(0xffffffffu, pa0[c], off);
            pa1[c] += __shfl_xor_sync(0xffffffffu, pa1[c], off);
        }
    }
    if (lane == 0) {
        #pragma unroll
        for (int c = 0; c < HIDD; c++) {
            attn_s[c * 16 + r0] = pa0[c];
            attn_s[c * 16 + r1] = pa1[c];
        }
    }
    __syncthreads();

    if (tid < 48) {
        int o = tid >> 4, r = tid & 15;
        float a = 0.f;
        #pragma unroll
        for (int c = 0; c < HIDD; c++) a += W3[o * HIDD + c] * attn_s[c * 16 + r];
        g_A3[((size_t)b * 3 + o) * EDIM + e0 + r] = a;
    }
}

// ---------------------------------------------------------------------------
// Stage 3: out[b,o,t] = p[b,o,t] + sum_e A3[b,o,e] Wo[t,e] + rowsum(W3)[o]*bo[t]
// ---------------------------------------------------------------------------
__global__ __launch_bounds__(256) void final_kernel(
    const float* __restrict__ x, const float* __restrict__ Wo,
    const float* __restrict__ bo, const float* __restrict__ W3,
    float* __restrict__ out)
{
    int b = blockIdx.x;
    int tid = threadIdx.x;
    int ta = blockIdx.y * 512 + tid;
    int tb = ta + 256;

    __shared__ float a3s[3 * EDIM];
    __shared__ float w3s[3];
    for (int i = tid; i < 3 * EDIM; i += 256) a3s[i] = g_A3[(size_t)b * 3 * EDIM + i];
    if (tid < 3) {
        float s = 0.f;
        #pragma unroll
        for (int c = 0; c < HIDD; c++) s += W3[tid * HIDD + c];
        w3s[tid] = s;
    }
    __syncthreads();

    const float4* wra = (const float4*)(Wo + (size_t)ta * EDIM);
    const float4* wrb = (const float4*)(Wo + (size_t)tb * EDIM);
    const float4* a0 = (const float4*)(a3s);
    const float4* a1 = (const float4*)(a3s + EDIM);
    const float4* a2 = (const float4*)(a3s + 2 * EDIM);

    float a00 = 0.f, a01 = 0.f, a02 = 0.f;
    float a10 = 0.f, a11 = 0.f, a12 = 0.f;
    #pragma unroll 4
    for (int e = 0; e < EDIM / 4; e++) {
        float4 wa = wra[e];
        float4 wb = wrb[e];
        float4 v0 = a0[e], v1 = a1[e], v2 = a2[e];
        a00 += wa.x * v0.x + wa.y * v0.y + wa.z * v0.z + wa.w * v0.w;
        a01 += wa.x * v1.x + wa.y * v1.y + wa.z * v1.z + wa.w * v1.w;
        a02 += wa.x * v2.x + wa.y * v2.y + wa.z * v2.z + wa.w * v2.w;
        a10 += wb.x * v0.x + wb.y * v0.y + wb.z * v0.z + wb.w * v0.w;
        a11 += wb.x * v1.x + wb.y * v1.y + wb.z * v1.z + wb.w * v1.w;
        a12 += wb.x * v2.x + wb.y * v2.y + wb.z * v2.z + wb.w * v2.w;
    }
    float boa = bo[ta], bob = bo[tb];
    out[((size_t)b * 3 + 0) * TDIM + ta] = x[((size_t)b * 7 + 0) * TDIM + ta] + a00 + w3s[0] * boa;
    out[((size_t)b * 3 + 1) * TDIM + ta] = x[((size_t)b * 7 + 1) * TDIM + ta] + a01 + w3s[1] * boa;
    out[((size_t)b * 3 + 2) * TDIM + ta] = x[((size_t)b * 7 + 2) * TDIM + ta] + a02 + w3s[2] * boa;
    out[((size_t)b * 3 + 0) * TDIM + tb] = x[((size_t)b * 7 + 0) * TDIM + tb] + a10 + w3s[0] * bob;
    out[((size_t)b * 3 + 1) * TDIM + tb] = x[((size_t)b * 7 + 1) * TDIM + tb] + a11 + w3s[1] * bob;
    out[((size_t)b * 3 + 2) * TDIM + tb] = x[((size_t)b * 7 + 2) * TDIM + tb] + a12 + w3s[2] * bob;
}

// ---------------------------------------------------------------------------
extern "C" void kernel_launch(void* const* d_in, const int* in_sizes, int n_in,
                              void* d_out, int out_size)
{
    const float* x  = (const float*)d_in[0];
    const float* W1 = (const float*)d_in[1];
    const float* W2 = (const float*)d_in[2];
    const float* Wq = (const float*)d_in[3];
    const float* bq = (const float*)d_in[4];
    const float* Wk = (const float*)d_in[5];
    const float* bk = (const float*)d_in[6];
    const float* Wv = (const float*)d_in[7];
    const float* bv = (const float*)d_in[8];
    const float* Wo = (const float*)d_in[9];
    const float* bo = (const float*)d_in[10];
    const float* W3 = (const float*)d_in[11];
    float* out = (float*)d_out;

    cudaFuncSetAttribute(stage1_mma, cudaFuncAttributeMaxDynamicSharedMemorySize, SMEM_S1);

    stage1_mma<<<dim3(24, KS), 512, SMEM_S1>>>(x, Wq, Wk, Wv);
    reduce_part<<<(NROWS * EDIM + 255) / 256, 256>>>();
    qkv_kernel<<<BDIM, 256>>>(W1, W2, bq, bk, bv);
    attn_kernel<<<dim3(BDIM, EDIM / 16), 256>>>(W3);
    final_kernel<<<dim3(BDIM, TDIM / 512), 256>>>(x, Wo, bo, W3, out);
}

// round 11
// speedup vs baseline: 5.7209x; 2.3313x over previous
#include <cuda_runtime.h>
#include <cuda_fp16.h>
#include <math.h>

#define TDIM 16384
#define BDIM 64
#define EDIM 512
#define HIDD 16
#define NROWS 704            // compact: 192 (P~) + 256 (K~) + 256 (V~)
#define PROWS 768            // padded : 256 + 256 + 256
#define KS 6                 // split-K ways for stage1

// Scratch (static device globals; no allocation at runtime)
__device__ float g_part[KS * PROWS * EDIM];       // split-K partials (9.4 MB)
__device__ float g_Tt[NROWS * EDIM];              // reduced tildes (compact)
__device__ float g_Q[BDIM * HIDD * EDIM];
__device__ float g_K[BDIM * HIDD * EDIM];
__device__ float g_V[BDIM * HIDD * EDIM];
__device__ float g_A3[BDIM * 3 * EDIM];

// ---------------------------------------------------------------------------
// MMA / ldmatrix helpers (fp16 m16n8k16, fp32 accum)
// ---------------------------------------------------------------------------
__device__ __forceinline__ void ldmx4(unsigned &r0, unsigned &r1, unsigned &r2,
                                      unsigned &r3, unsigned addr) {
    asm volatile("ldmatrix.sync.aligned.m8n8.x4.shared.b16 {%0,%1,%2,%3}, [%4];"
                 : "=r"(r0), "=r"(r1), "=r"(r2), "=r"(r3) : "r"(addr));
}
__device__ __forceinline__ void ldmx2(unsigned &r0, unsigned &r1, unsigned addr) {
    asm volatile("ldmatrix.sync.aligned.m8n8.x2.shared.b16 {%0,%1}, [%2];"
                 : "=r"(r0), "=r"(r1) : "r"(addr));
}
__device__ __forceinline__ void mma16816(float *c, const unsigned *a, const unsigned *b) {
    asm volatile(
        "mma.sync.aligned.m16n8k16.row.col.f32.f16.f16.f32 "
        "{%0,%1,%2,%3}, {%4,%5,%6,%7}, {%8,%9}, {%0,%1,%2,%3};"
        : "+f"(c[0]), "+f"(c[1]), "+f"(c[2]), "+f"(c[3])
        : "r"(a[0]), "r"(a[1]), "r"(a[2]), "r"(a[3]), "r"(b[0]), "r"(b[1]));
}

// 8 consecutive fp32 -> 8 fp16 (hi only), packed for STS.128
__device__ __forceinline__ void cvt8h(const float *f, uint4 &hi) {
    __half2 h01 = __floats2half2_rn(f[0], f[1]);
    __half2 h23 = __floats2half2_rn(f[2], f[3]);
    __half2 h45 = __floats2half2_rn(f[4], f[5]);
    __half2 h67 = __floats2half2_rn(f[6], f[7]);
    hi.x = *(unsigned*)&h01; hi.y = *(unsigned*)&h23;
    hi.z = *(unsigned*)&h45; hi.w = *(unsigned*)&h67;
}
// 8 consecutive fp32 -> fp16 hi + fp16 lo (residual), packed for STS.128
__device__ __forceinline__ void cvt8hl(const float *f, uint4 &hi, uint4 &lo) {
    #pragma unroll
    for (int i = 0; i < 4; i++) {
        __half2 h = __floats2half2_rn(f[2*i], f[2*i+1]);
        float2 hf = __half22float2(h);
        __half2 l = __floats2half2_rn(f[2*i] - hf.x, f[2*i+1] - hf.y);
        (&hi.x)[i] = *(unsigned*)&h;
        (&lo.x)[i] = *(unsigned*)&l;
    }
}

// ---------------------------------------------------------------------------
// Stage 1 (tensor, fp16 2-term): C[r][e] = sum_t A[r][t] * W[e][t]
//   padded rows [0,256)   : Xp (192 valid) . Wq^T
//   padded rows [256,512) : Xc . Wk^T
//   padded rows [512,768) : Xc . Wv^T
// CTA: 128x128 tile, 512 threads (4x4 warps of 32x32), k-step 32,
// double-buffered fp16 smem tiles:  D += Ah.(Bh + Bl)^T
// ---------------------------------------------------------------------------
#define LDB 40                         // fp16 row stride (80 B) - conflict-free ldmatrix
#define TILEB (128 * LDB)              // fp16 elements per buffer per tile
#define SMEM_S1 (3 * 2 * TILEB * 2)    // bytes: Ah,Bh,Bl x 2 buffers x 2B  (~60 KB)

__global__ __launch_bounds__(512, 1) void stage1_mma(
    const float* __restrict__ x, const float* __restrict__ Wq,
    const float* __restrict__ Wk, const float* __restrict__ Wv)
{
    extern __shared__ unsigned short dynsm[];
    unsigned short* Ah = dynsm;
    unsigned short* Bh = Ah + 2 * TILEB;
    unsigned short* Bl = Bh + 2 * TILEB;

    int mt = blockIdx.x >> 2;          // 0..5
    int nt = blockIdx.x & 3;           // 0..3
    int ks = blockIdx.y;               // 0..5
    int k0 = ks * 2752;
    int len = (ks < 5) ? 2752 : 2624;
    int nIter = len >> 5;              // k-steps of 32

    const float* W = (mt < 2) ? Wq : (mt < 4 ? Wk : Wv);

    int tid  = threadIdx.x;
    int lane = tid & 31;
    int wid  = tid >> 5;               // 0..15
    int wm   = wid >> 2;               // warp m 0..3 (32 rows each)
    int wn   = wid & 3;                // warp n 0..3 (32 cols each)

    // ---- global load mapping: each thread owns (row, 8-k-slice) ----
    int lrow = tid >> 2;               // 0..127
    int kq8  = (tid & 3) << 3;         // 0,8,16,24

    int pr = mt * 128 + lrow;          // padded stacked row
    int mat = pr >> 8, loc = pr & 255;
    int xrow;
    if (mat == 0) xrow = (loc < 192) ? ((loc / 3) * 7 + (loc % 3)) : 0;
    else          xrow = (loc >> 2) * 7 + 3 + (loc & 3);
    const float* pA = x + (size_t)xrow * TDIM + k0 + kq8;
    const float* pB = W + (size_t)(nt * 128 + lrow) * TDIM + k0 + kq8;

    int sidx = lrow * LDB + kq8;       // within-buffer element index

    float acc[2][4][4];
    #pragma unroll
    for (int mi = 0; mi < 2; mi++)
        #pragma unroll
        for (int ni = 0; ni < 4; ni++)
            #pragma unroll
            for (int r = 0; r < 4; r++) acc[mi][ni][r] = 0.f;

    // ---- preload iter 0 ----
    float fa[8], fb[8];
    *(float4*)&fa[0] = *(const float4*)pA;  *(float4*)&fa[4] = *(const float4*)(pA + 4);
    *(float4*)&fb[0] = *(const float4*)pB;  *(float4*)&fb[4] = *(const float4*)(pB + 4);
    {
        uint4 hi, lo;
        cvt8h(fa, hi);
        *(uint4*)&Ah[sidx] = hi;
        cvt8hl(fb, hi, lo);
        *(uint4*)&Bh[sidx] = hi; *(uint4*)&Bl[sidx] = lo;
    }
    __syncthreads();

    unsigned baseAh = (unsigned)__cvta_generic_to_shared(Ah);
    unsigned baseBh = (unsigned)__cvta_generic_to_shared(Bh);
    unsigned baseBl = (unsigned)__cvta_generic_to_shared(Bl);

    // per-lane ldmatrix row/col offsets
    int aRow = wm * 32 + (lane & 15);            // + mi*16
    int aCol = (lane >> 4) << 3;                 // + k16
    int bRow = wn * 32 + (lane & 7);             // + ni*8
    int bCol = ((lane >> 3) & 1) << 3;           // + k16

    for (int it = 0; it < nIter; it++) {
        int buf = it & 1;
        bool more = (it + 1 < nIter);
        if (more) {
            const float* qA = pA + (it + 1) * 32;
            const float* qB = pB + (it + 1) * 32;
            *(float4*)&fa[0] = *(const float4*)qA;  *(float4*)&fa[4] = *(const float4*)(qA + 4);
            *(float4*)&fb[0] = *(const float4*)qB;  *(float4*)&fb[4] = *(const float4*)(qB + 4);
        }

        unsigned bufOff = (unsigned)(buf * TILEB * 2);  // bytes
        #pragma unroll
        for (int kk = 0; kk < 2; kk++) {
            int k16 = kk << 4;
            unsigned bh[4][2], bl[4][2];
            #pragma unroll
            for (int ni = 0; ni < 4; ni++) {
                unsigned off = bufOff + (unsigned)((bRow + ni * 8) * LDB + (bCol + k16)) * 2u;
                ldmx2(bh[ni][0], bh[ni][1], baseBh + off);
                ldmx2(bl[ni][0], bl[ni][1], baseBl + off);
            }
            #pragma unroll
            for (int mi = 0; mi < 2; mi++) {
                unsigned off = bufOff + (unsigned)((aRow + mi * 16) * LDB + (aCol + k16)) * 2u;
                unsigned ah[4];
                ldmx4(ah[0], ah[1], ah[2], ah[3], baseAh + off);
                #pragma unroll
                for (int ni = 0; ni < 4; ni++) {
                    mma16816(acc[mi][ni], ah, bh[ni]);
                    mma16816(acc[mi][ni], ah, bl[ni]);
                }
            }
        }

        if (more) {
            int d = ((buf ^ 1) * TILEB) + sidx;
            uint4 hi, lo;
            cvt8h(fa, hi);
            *(uint4*)&Ah[d] = hi;
            cvt8hl(fb, hi, lo);
            *(uint4*)&Bh[d] = hi; *(uint4*)&Bl[d] = lo;
        }
        __syncthreads();
    }

    // ---- store accumulators to padded split-K scratch ----
    float* base = g_part + ((size_t)ks * PROWS + mt * 128 + wm * 32) * EDIM
                + nt * 128 + wn * 32;
    int rr = lane >> 2, cc = (lane & 3) << 1;
    #pragma unroll
    for (int mi = 0; mi < 2; mi++)
        #pragma unroll
        for (int ni = 0; ni < 4; ni++) {
            float* p0 = base + (size_t)(mi * 16 + rr) * EDIM + ni * 8 + cc;
            *(float2*)p0              = make_float2(acc[mi][ni][0], acc[mi][ni][1]);
            *(float2*)(p0 + 8 * EDIM) = make_float2(acc[mi][ni][2], acc[mi][ni][3]);
        }
}

// ---------------------------------------------------------------------------
__global__ void reduce_part()
{
    int i = blockIdx.x * 256 + threadIdx.x;
    if (i < NROWS * EDIM) {
        int r = i >> 9, e = i & 511;
        int pr = (r < 192) ? r : (r + 64);       // compact -> padded row
        size_t pi = (size_t)pr * EDIM + e;
        float s = 0.f;
        #pragma unroll
        for (int k = 0; k < KS; k++) s += g_part[(size_t)k * PROWS * EDIM + pi];
        g_Tt[i] = s;
    }
}

// ---------------------------------------------------------------------------
// Stage 2a: Q = W1 . P~ + bq ; K = W2 . K~ + bk ; V = W2 . V~ + bv (per batch)
// ---------------------------------------------------------------------------
__global__ __launch_bounds__(256) void qkv_kernel(
    const float* __restrict__ W1, const float* __restrict__ W2,
    const float* __restrict__ bq, const float* __restrict__ bk,
    const float* __restrict__ bv)
{
    int b = blockIdx.x;
    __shared__ float w1s[HIDD * 3];
    __shared__ float w2s[HIDD * 4];
    int tid = threadIdx.x;
    if (tid < HIDD * 3) w1s[tid] = W1[tid];
    if (tid < HIDD * 4) w2s[tid] = W2[tid];
    __syncthreads();

    for (int e = tid; e < EDIM; e += 256) {
        float pt[3], kt[4], vt[4];
        #pragma unroll
        for (int c = 0; c < 3; c++) pt[c] = g_Tt[(b * 3 + c) * EDIM + e];
        #pragma unroll
        for (int c = 0; c < 4; c++) kt[c] = g_Tt[(192 + b * 4 + c) * EDIM + e];
        #pragma unroll
        for (int c = 0; c < 4; c++) vt[c] = g_Tt[(448 + b * 4 + c) * EDIM + e];
        float bqv = bq[e], bkv = bk[e], bvv = bv[e];
        #pragma unroll
        for (int o = 0; o < HIDD; o++) {
            float q = bqv, kk = bkv, vv = bvv;
            #pragma unroll
            for (int c = 0; c < 3; c++) q += w1s[o * 3 + c] * pt[c];
            #pragma unroll
            for (int c = 0; c < 4; c++) { kk += w2s[o * 4 + c] * kt[c]; vv += w2s[o * 4 + c] * vt[c]; }
            g_Q[((size_t)b * HIDD + o) * EDIM + e] = q;
            g_K[((size_t)b * HIDD + o) * EDIM + e] = kk;
            g_V[((size_t)b * HIDD + o) * EDIM + e] = vv;
        }
    }
}

// ---------------------------------------------------------------------------
// Stage 2b: per (b, 16-row e-tile): softmax attention, fused W3 projection.
// ---------------------------------------------------------------------------
__global__ __launch_bounds__(256) void attn_kernel(const float* __restrict__ W3)
{
    int b = blockIdx.x, e0 = blockIdx.y * 16;
    __shared__ float KVs[HIDD * EDIM];   // 32 KB, reused K then V
    __shared__ float Qs[HIDD * 16];
    __shared__ float attn_s[HIDD * 16];

    int tid = threadIdx.x, lane = tid & 31, w = tid >> 5;

    {
        const float4* src = (const float4*)(g_K + (size_t)b * HIDD * EDIM);
        float4* dst = (float4*)KVs;
        for (int i = tid; i < HIDD * EDIM / 4; i += 256) dst[i] = src[i];
        int c = tid >> 4, r = tid & 15;
        Qs[c * 16 + r] = g_Q[((size_t)b * HIDD + c) * EDIM + e0 + r] * 0.25f;
    }
    __syncthreads();

    int r0 = w * 2, r1 = r0 + 1;
    float q0[HIDD], q1[HIDD];
    #pragma unroll
    for (int c = 0; c < HIDD; c++) { q0[c] = Qs[c * 16 + r0]; q1[c] = Qs[c * 16 + r1]; }

    float s0[16], s1[16];
    #pragma unroll
    for (int j = 0; j < 16; j++) {
        int f = lane + 32 * j;
        float a = 0.f, bb = 0.f;
        #pragma unroll
        for (int c = 0; c < HIDD; c++) {
            float kv = KVs[c * EDIM + f];
            a += q0[c] * kv; bb += q1[c] * kv;
        }
        s0[j] = a; s1[j] = bb;
    }

    #pragma unroll
    for (int rr = 0; rr < 2; rr++) {
        float* s = rr ? s1 : s0;
        float m = s[0];
        #pragma unroll
        for (int j = 1; j < 16; j++) m = fmaxf(m, s[j]);
        #pragma unroll
        for (int off = 16; off > 0; off >>= 1) m = fmaxf(m, __shfl_xor_sync(0xffffffffu, m, off));
        float sum = 0.f;
        #pragma unroll
        for (int j = 0; j < 16; j++) { s[j] = __expf(s[j] - m); sum += s[j]; }
        #pragma unroll
        for (int off = 16; off > 0; off >>= 1) sum += __shfl_xor_sync(0xffffffffu, sum, off);
        float inv = 1.f / sum;
        #pragma unroll
        for (int j = 0; j < 16; j++) s[j] *= inv;
    }

    __syncthreads();
    {
        const float4* src = (const float4*)(g_V + (size_t)b * HIDD * EDIM);
        float4* dst = (float4*)KVs;
        for (int i = tid; i < HIDD * EDIM / 4; i += 256) dst[i] = src[i];
    }
    __syncthreads();

    float pa0[HIDD], pa1[HIDD];
    #pragma unroll
    for (int c = 0; c < HIDD; c++) { pa0[c] = 0.f; pa1[c] = 0.f; }
    #pragma unroll
    for (int j = 0; j < 16; j++) {
        int f = lane + 32 * j;
        float w0 = s0[j], w1 = s1[j];
        #pragma unroll
        for (int c = 0; c < HIDD; c++) {
            float vv = KVs[c * EDIM + f];
            pa0[c] += w0 * vv; pa1[c] += w1 * vv;
        }
    }
    #pragma unroll
    for (int off = 16; off > 0; off >>= 1) {
        #pragma unroll
        for (int c = 0; c < HIDD; c++) {
            pa0[c] += __shfl_xor_sync(0xffffffffu, pa0[c], off);
            pa1[c] += __shfl_xor_sync(0xffffffffu, pa1[c], off);
        }
    }
    if (lane == 0) {
        #pragma unroll
        for (int c = 0; c < HIDD; c++) {
            attn_s[c * 16 + r0] = pa0[c];
            attn_s[c * 16 + r1] = pa1[c];
        }
    }
    __syncthreads();

    if (tid < 48) {
        int o = tid >> 4, r = tid & 15;
        float a = 0.f;
        #pragma unroll
        for (int c = 0; c < HIDD; c++) a += W3[o * HIDD + c] * attn_s[c * 16 + r];
        g_A3[((size_t)b * 3 + o) * EDIM + e0 + r] = a;
    }
}

// ---------------------------------------------------------------------------
// Stage 3: out[b,o,t] = p[b,o,t] + sum_e A3[b,o,e] Wo[t,e] + rowsum(W3)[o]*bo[t]
// Re-tiled for Wo reuse: CTA = 512 t-block x 8-batch chunk; A3 chunk in smem.
// Wo L2 traffic drops from 64x to 8x its size.
// ---------------------------------------------------------------------------
__global__ __launch_bounds__(256) void final2(
    const float* __restrict__ x, const float* __restrict__ Wo,
    const float* __restrict__ bo, const float* __restrict__ W3,
    float* __restrict__ out)
{
    __shared__ float a3s[8 * 3 * EDIM];   // 48 KB
    int tid = threadIdx.x;
    int b0 = blockIdx.y * 8;
    int ta = blockIdx.x * 512 + tid;
    int tb = ta + 256;

    for (int i = tid; i < 8 * 3 * EDIM; i += 256)
        a3s[i] = g_A3[(size_t)b0 * 3 * EDIM + i];

    float w3s[3];
    #pragma unroll
    for (int o = 0; o < 3; o++) {
        float s = 0.f;
        #pragma unroll
        for (int c = 0; c < HIDD; c++) s += W3[o * HIDD + c];
        w3s[o] = s;
    }
    __syncthreads();

    const float4* wra = (const float4*)(Wo + (size_t)ta * EDIM);
    const float4* wrb = (const float4*)(Wo + (size_t)tb * EDIM);
    const float4* a3v = (const float4*)a3s;

    float acc0[8][3], acc1[8][3];
    #pragma unroll
    for (int bb = 0; bb < 8; bb++)
        #pragma unroll
        for (int o = 0; o < 3; o++) { acc0[bb][o] = 0.f; acc1[bb][o] = 0.f; }

    for (int e = 0; e < EDIM / 4; e++) {
        float4 wa = wra[e];
        float4 wb = wrb[e];
        #pragma unroll
        for (int bb = 0; bb < 8; bb++)
            #pragma unroll
            for (int o = 0; o < 3; o++) {
                float4 v = a3v[(bb * 3 + o) * (EDIM / 4) + e];
                acc0[bb][o] += wa.x * v.x + wa.y * v.y + wa.z * v.z + wa.w * v.w;
                acc1[bb][o] += wb.x * v.x + wb.y * v.y + wb.z * v.z + wb.w * v.w;
            }
    }

    float boa = bo[ta], bob = bo[tb];
    #pragma unroll
    for (int bb = 0; bb < 8; bb++)
        #pragma unroll
        for (int o = 0; o < 3; o++) {
            size_t ob = ((size_t)(b0 + bb) * 3 + o) * TDIM;
            size_t xb = ((size_t)(b0 + bb) * 7 + o) * TDIM;
            out[ob + ta] = x[xb + ta] + acc0[bb][o] + w3s[o] * boa;
            out[ob + tb] = x[xb + tb] + acc1[bb][o] + w3s[o] * bob;
        }
}

// ---------------------------------------------------------------------------
extern "C" void kernel_launch(void* const* d_in, const int* in_sizes, int n_in,
                              void* d_out, int out_size)
{
    const float* x  = (const float*)d_in[0];
    const float* W1 = (const float*)d_in[1];
    const float* W2 = (const float*)d_in[2];
    const float* Wq = (const float*)d_in[3];
    const float* bq = (const float*)d_in[4];
    const float* Wk = (const float*)d_in[5];
    const float* bk = (const float*)d_in[6];
    const float* Wv = (const float*)d_in[7];
    const float* bv = (const float*)d_in[8];
    const float* Wo = (const float*)d_in[9];
    const float* bo = (const float*)d_in[10];
    const float* W3 = (const float*)d_in[11];
    float* out = (float*)d_out;

    cudaFuncSetAttribute(stage1_mma, cudaFuncAttributeMaxDynamicSharedMemorySize, SMEM_S1);

    stage1_mma<<<dim3(24, KS), 512, SMEM_S1>>>(x, Wq, Wk, Wv);
    reduce_part<<<(NROWS * EDIM + 255) / 256, 256>>>();
    qkv_kernel<<<BDIM, 256>>>(W1, W2, bq, bk, bv);
    attn_kernel<<<dim3(BDIM, EDIM / 16), 256>>>(W3);
    final2<<<dim3(TDIM / 512, BDIM / 8), 256>>>(x, Wo, bo, W3, out);
}

// round 12
// speedup vs baseline: 6.0530x; 1.0581x over previous
#include <cuda_runtime.h>
#include <cuda_fp16.h>
#include <math.h>

#define TDIM 16384
#define BDIM 64
#define EDIM 512
#define HIDD 16
#define PROWS 768            // padded rows: 256 (P~) + 256 (K~) + 256 (V~)
#define KS 12                // split-K ways for stage1

// Scratch (static device globals; no allocation at runtime)
__device__ float g_part[KS * PROWS * EDIM];       // split-K partials (18.9 MB)
__device__ float g_Q[BDIM * HIDD * EDIM];
__device__ float g_K[BDIM * HIDD * EDIM];
__device__ float g_V[BDIM * HIDD * EDIM];
__device__ float g_A3[BDIM * 3 * EDIM];

// ---------------------------------------------------------------------------
// MMA / ldmatrix helpers (fp16 m16n8k16, fp32 accum)
// ---------------------------------------------------------------------------
__device__ __forceinline__ void ldmx4(unsigned &r0, unsigned &r1, unsigned &r2,
                                      unsigned &r3, unsigned addr) {
    asm volatile("ldmatrix.sync.aligned.m8n8.x4.shared.b16 {%0,%1,%2,%3}, [%4];"
                 : "=r"(r0), "=r"(r1), "=r"(r2), "=r"(r3) : "r"(addr));
}
__device__ __forceinline__ void ldmx2(unsigned &r0, unsigned &r1, unsigned addr) {
    asm volatile("ldmatrix.sync.aligned.m8n8.x2.shared.b16 {%0,%1}, [%2];"
                 : "=r"(r0), "=r"(r1) : "r"(addr));
}
__device__ __forceinline__ void mma16816(float *c, const unsigned *a, const unsigned *b) {
    asm volatile(
        "mma.sync.aligned.m16n8k16.row.col.f32.f16.f16.f32 "
        "{%0,%1,%2,%3}, {%4,%5,%6,%7}, {%8,%9}, {%0,%1,%2,%3};"
        : "+f"(c[0]), "+f"(c[1]), "+f"(c[2]), "+f"(c[3])
        : "r"(a[0]), "r"(a[1]), "r"(a[2]), "r"(a[3]), "r"(b[0]), "r"(b[1]));
}

// 8 consecutive fp32 -> 8 fp16, packed for STS.128
__device__ __forceinline__ void cvt8h(const float *f, uint4 &hi) {
    __half2 h01 = __floats2half2_rn(f[0], f[1]);
    __half2 h23 = __floats2half2_rn(f[2], f[3]);
    __half2 h45 = __floats2half2_rn(f[4], f[5]);
    __half2 h67 = __floats2half2_rn(f[6], f[7]);
    hi.x = *(unsigned*)&h01; hi.y = *(unsigned*)&h23;
    hi.z = *(unsigned*)&h45; hi.w = *(unsigned*)&h67;
}

// ---------------------------------------------------------------------------
// Stage 1 (tensor, fp16 single-term): C[r][e] = sum_t A[r][t] * W[e][t]
//   padded rows [0,256)   : Xp (192 valid) . Wq^T
//   padded rows [256,512) : Xc . Wk^T
//   padded rows [512,768) : Xc . Wv^T
// CTA: 128x128 tile, 512 threads (4x4 warps of 32x32), k-step 32,
// double-buffered fp16 smem tiles:  D += A.B^T  (fp32 accum in regs)
// Split-K 12: ks<4 -> 22 k-steps, else 21 (total 256 steps of 64... of 32x2).
// ---------------------------------------------------------------------------
#define LDB 40                         // fp16 row stride (80 B) - conflict-free ldmatrix
#define TILEB (128 * LDB)              // fp16 elements per buffer per tile
#define SMEM_S1 (2 * 2 * TILEB * 2)    // bytes: A,B x 2 buffers x 2B  (40 KB)

__global__ __launch_bounds__(512, 2) void stage1_mma(
    const float* __restrict__ x, const float* __restrict__ Wq,
    const float* __restrict__ Wk, const float* __restrict__ Wv)
{
    extern __shared__ unsigned short dynsm[];
    unsigned short* Ah = dynsm;
    unsigned short* Bh = Ah + 2 * TILEB;

    int mt = blockIdx.x >> 2;          // 0..5
    int nt = blockIdx.x & 3;           // 0..3
    int ks = blockIdx.y;               // 0..11
    int stepBase = (ks < 4) ? ks * 22 : 88 + (ks - 4) * 21;
    int nIter = (ks < 4) ? 22 : 21;    // k-steps of 32
    int k0 = stepBase * 32 * 2;        // NOTE: steps are 32 wide; 256*... 

    // Correct: 256 total 64-wide? No — steps are 32 elements; total steps = 512.
    // Recompute: TDIM/32 = 512 steps; 12 ways: 8 blocks of 43, 4 blocks of 42.
    stepBase = (ks < 8) ? ks * 43 : 344 + (ks - 8) * 42;
    nIter = (ks < 8) ? 43 : 42;        // 8*43 + 4*42 = 512
    k0 = stepBase * 32;

    const float* W = (mt < 2) ? Wq : (mt < 4 ? Wk : Wv);

    int tid  = threadIdx.x;
    int lane = tid & 31;
    int wid  = tid >> 5;               // 0..15
    int wm   = wid >> 2;               // warp m 0..3 (32 rows each)
    int wn   = wid & 3;                // warp n 0..3 (32 cols each)

    // ---- global load mapping: each thread owns (row, 8-k-slice) ----
    int lrow = tid >> 2;               // 0..127
    int kq8  = (tid & 3) << 3;         // 0,8,16,24

    int pr = mt * 128 + lrow;          // padded stacked row
    int mat = pr >> 8, loc = pr & 255;
    int xrow;
    if (mat == 0) xrow = (loc < 192) ? ((loc / 3) * 7 + (loc % 3)) : 0;
    else          xrow = (loc >> 2) * 7 + 3 + (loc & 3);
    const float* pA = x + (size_t)xrow * TDIM + k0 + kq8;
    const float* pB = W + (size_t)(nt * 128 + lrow) * TDIM + k0 + kq8;

    int sidx = lrow * LDB + kq8;       // within-buffer element index

    float acc[2][4][4];
    #pragma unroll
    for (int mi = 0; mi < 2; mi++)
        #pragma unroll
        for (int ni = 0; ni < 4; ni++)
            #pragma unroll
            for (int r = 0; r < 4; r++) acc[mi][ni][r] = 0.f;

    // ---- preload iter 0 ----
    float fa[8], fb[8];
    *(float4*)&fa[0] = *(const float4*)pA;  *(float4*)&fa[4] = *(const float4*)(pA + 4);
    *(float4*)&fb[0] = *(const float4*)pB;  *(float4*)&fb[4] = *(const float4*)(pB + 4);
    {
        uint4 hi;
        cvt8h(fa, hi);
        *(uint4*)&Ah[sidx] = hi;
        cvt8h(fb, hi);
        *(uint4*)&Bh[sidx] = hi;
    }
    __syncthreads();

    unsigned baseAh = (unsigned)__cvta_generic_to_shared(Ah);
    unsigned baseBh = (unsigned)__cvta_generic_to_shared(Bh);

    // per-lane ldmatrix row/col offsets
    int aRow = wm * 32 + (lane & 15);            // + mi*16
    int aCol = (lane >> 4) << 3;                 // + k16
    int bRow = wn * 32 + (lane & 7);             // + ni*8
    int bCol = ((lane >> 3) & 1) << 3;           // + k16

    for (int it = 0; it < nIter; it++) {
        int buf = it & 1;
        bool more = (it + 1 < nIter);
        if (more) {
            const float* qA = pA + (it + 1) * 32;
            const float* qB = pB + (it + 1) * 32;
            *(float4*)&fa[0] = *(const float4*)qA;  *(float4*)&fa[4] = *(const float4*)(qA + 4);
            *(float4*)&fb[0] = *(const float4*)qB;  *(float4*)&fb[4] = *(const float4*)(qB + 4);
        }

        unsigned bufOff = (unsigned)(buf * TILEB * 2);  // bytes
        #pragma unroll
        for (int kk = 0; kk < 2; kk++) {
            int k16 = kk << 4;
            unsigned bh[4][2];
            #pragma unroll
            for (int ni = 0; ni < 4; ni++) {
                unsigned off = bufOff + (unsigned)((bRow + ni * 8) * LDB + (bCol + k16)) * 2u;
                ldmx2(bh[ni][0], bh[ni][1], baseBh + off);
            }
            #pragma unroll
            for (int mi = 0; mi < 2; mi++) {
                unsigned off = bufOff + (unsigned)((aRow + mi * 16) * LDB + (aCol + k16)) * 2u;
                unsigned ah[4];
                ldmx4(ah[0], ah[1], ah[2], ah[3], baseAh + off);
                #pragma unroll
                for (int ni = 0; ni < 4; ni++)
                    mma16816(acc[mi][ni], ah, bh[ni]);
            }
        }

        if (more) {
            int d = ((buf ^ 1) * TILEB) + sidx;
            uint4 hi;
            cvt8h(fa, hi);
            *(uint4*)&Ah[d] = hi;
            cvt8h(fb, hi);
            *(uint4*)&Bh[d] = hi;
        }
        __syncthreads();
    }

    // ---- store accumulators to padded split-K scratch ----
    float* base = g_part + ((size_t)ks * PROWS + mt * 128 + wm * 32) * EDIM
                + nt * 128 + wn * 32;
    int rr = lane >> 2, cc = (lane & 3) << 1;
    #pragma unroll
    for (int mi = 0; mi < 2; mi++)
        #pragma unroll
        for (int ni = 0; ni < 4; ni++) {
            float* p0 = base + (size_t)(mi * 16 + rr) * EDIM + ni * 8 + cc;
            *(float2*)p0              = make_float2(acc[mi][ni][0], acc[mi][ni][1]);
            *(float2*)(p0 + 8 * EDIM) = make_float2(acc[mi][ni][2], acc[mi][ni][3]);
        }
}

// ---------------------------------------------------------------------------
// Stage 2a (fused reduce): Q/K/V = small projections of split-K-summed tildes.
// Padded rows: P~ row (b*3+c); K~ row 256+(b*4+c); V~ row 512+(b*4+c).
// ---------------------------------------------------------------------------
__global__ __launch_bounds__(256) void qkv_kernel(
    const float* __restrict__ W1, const float* __restrict__ W2,
    const float* __restrict__ bq, const float* __restrict__ bk,
    const float* __restrict__ bv)
{
    int b = blockIdx.x;
    __shared__ float w1s[HIDD * 3];
    __shared__ float w2s[HIDD * 4];
    int tid = threadIdx.x;
    if (tid < HIDD * 3) w1s[tid] = W1[tid];
    if (tid < HIDD * 4) w2s[tid] = W2[tid];
    __syncthreads();

    for (int e = tid; e < EDIM; e += 256) {
        float pt[3], kt[4], vt[4];
        #pragma unroll
        for (int c = 0; c < 3; c++) {
            size_t pi = (size_t)(b * 3 + c) * EDIM + e;
            float s = 0.f;
            #pragma unroll
            for (int k = 0; k < KS; k++) s += g_part[(size_t)k * PROWS * EDIM + pi];
            pt[c] = s;
        }
        #pragma unroll
        for (int c = 0; c < 4; c++) {
            size_t pi = (size_t)(256 + b * 4 + c) * EDIM + e;
            float s = 0.f;
            #pragma unroll
            for (int k = 0; k < KS; k++) s += g_part[(size_t)k * PROWS * EDIM + pi];
            kt[c] = s;
        }
        #pragma unroll
        for (int c = 0; c < 4; c++) {
            size_t pi = (size_t)(512 + b * 4 + c) * EDIM + e;
            float s = 0.f;
            #pragma unroll
            for (int k = 0; k < KS; k++) s += g_part[(size_t)k * PROWS * EDIM + pi];
            vt[c] = s;
        }
        float bqv = bq[e], bkv = bk[e], bvv = bv[e];
        #pragma unroll
        for (int o = 0; o < HIDD; o++) {
            float q = bqv, kk = bkv, vv = bvv;
            #pragma unroll
            for (int c = 0; c < 3; c++) q += w1s[o * 3 + c] * pt[c];
            #pragma unroll
            for (int c = 0; c < 4; c++) { kk += w2s[o * 4 + c] * kt[c]; vv += w2s[o * 4 + c] * vt[c]; }
            g_Q[((size_t)b * HIDD + o) * EDIM + e] = q;
            g_K[((size_t)b * HIDD + o) * EDIM + e] = kk;
            g_V[((size_t)b * HIDD + o) * EDIM + e] = vv;
        }
    }
}

// ---------------------------------------------------------------------------
// Stage 2b: per (b, 16-row e-tile): softmax attention, fused W3 projection.
// K/V staged in smem as half2 -> crossbar bytes halved vs fp32.
// Each warp owns 2 e-rows; lane covers f-pairs f = 2*(lane+32*jj), jj=0..7.
// ---------------------------------------------------------------------------
__global__ __launch_bounds__(256) void attn_kernel(const float* __restrict__ W3)
{
    int b = blockIdx.x, e0 = blockIdx.y * 16;
    __shared__ unsigned KV2[HIDD * EDIM / 2];   // 16 KB, half2-packed, K then V
    __shared__ float Qs[HIDD * 16];
    __shared__ float attn_s[HIDD * 16];

    int tid = threadIdx.x, lane = tid & 31, w = tid >> 5;

    {   // load K tile, convert to half2
        const float4* src = (const float4*)(g_K + (size_t)b * HIDD * EDIM);
        for (int i = tid; i < HIDD * EDIM / 4; i += 256) {
            float4 v = src[i];
            __half2 h0 = __floats2half2_rn(v.x, v.y);
            __half2 h1 = __floats2half2_rn(v.z, v.w);
            KV2[i * 2]     = *(unsigned*)&h0;
            KV2[i * 2 + 1] = *(unsigned*)&h1;
        }
        int c = tid >> 4, r = tid & 15;
        Qs[c * 16 + r] = g_Q[((size_t)b * HIDD + c) * EDIM + e0 + r] * 0.25f;  // fold scale
    }
    __syncthreads();

    int r0 = w * 2, r1 = r0 + 1;
    float q0[HIDD], q1[HIDD];
    #pragma unroll
    for (int c = 0; c < HIDD; c++) { q0[c] = Qs[c * 16 + r0]; q1[c] = Qs[c * 16 + r1]; }

    float s0[16], s1[16];
    #pragma unroll
    for (int jj = 0; jj < 8; jj++) {
        int fp = lane + 32 * jj;          // half2 index
        float ae = 0.f, ao = 0.f, be = 0.f, bo = 0.f;
        #pragma unroll
        for (int c = 0; c < HIDD; c++) {
            unsigned kv = KV2[c * (EDIM / 2) + fp];
            float2 kf = __half22float2(*(__half2*)&kv);
            ae += q0[c] * kf.x; ao += q0[c] * kf.y;
            be += q1[c] * kf.x; bo += q1[c] * kf.y;
        }
        s0[2 * jj] = ae; s0[2 * jj + 1] = ao;
        s1[2 * jj] = be; s1[2 * jj + 1] = bo;
    }

    #pragma unroll
    for (int rr = 0; rr < 2; rr++) {
        float* s = rr ? s1 : s0;
        float m = s[0];
        #pragma unroll
        for (int j = 1; j < 16; j++) m = fmaxf(m, s[j]);
        #pragma unroll
        for (int off = 16; off > 0; off >>= 1) m = fmaxf(m, __shfl_xor_sync(0xffffffffu, m, off));
        float sum = 0.f;
        #pragma unroll
        for (int j = 0; j < 16; j++) { s[j] = __expf(s[j] - m); sum += s[j]; }
        #pragma unroll
        for (int off = 16; off > 0; off >>= 1) sum += __shfl_xor_sync(0xffffffffu, sum, off);
        float inv = 1.f / sum;
        #pragma unroll
        for (int j = 0; j < 16; j++) s[j] *= inv;
    }

    __syncthreads();   // everyone done reading K
    {   // overwrite with V (half2)
        const float4* src = (const float4*)(g_V + (size_t)b * HIDD * EDIM);
        for (int i = tid; i < HIDD * EDIM / 4; i += 256) {
            float4 v = src[i];
            __half2 h0 = __floats2half2_rn(v.x, v.y);
            __half2 h1 = __floats2half2_rn(v.z, v.w);
            KV2[i * 2]     = *(unsigned*)&h0;
            KV2[i * 2 + 1] = *(unsigned*)&h1;
        }
    }
    __syncthreads();

    float pa0[HIDD], pa1[HIDD];
    #pragma unroll
    for (int c = 0; c < HIDD; c++) { pa0[c] = 0.f; pa1[c] = 0.f; }
    #pragma unroll
    for (int jj = 0; jj < 8; jj++) {
        int fp = lane + 32 * jj;
        float w0e = s0[2 * jj], w0o = s0[2 * jj + 1];
        float w1e = s1[2 * jj], w1o = s1[2 * jj + 1];
        #pragma unroll
        for (int c = 0; c < HIDD; c++) {
            unsigned kv = KV2[c * (EDIM / 2) + fp];
            float2 vf = __half22float2(*(__half2*)&kv);
            pa0[c] += w0e * vf.x + w0o * vf.y;
            pa1[c] += w1e * vf.x + w1o * vf.y;
        }
    }
    #pragma unroll
    for (int off = 16; off > 0; off >>= 1) {
        #pragma unroll
        for (int c = 0; c < HIDD; c++) {
            pa0[c] += __shfl_xor_sync(0xffffffffu, pa0[c], off);
            pa1[c] += __shfl_xor_sync(0xffffffffu, pa1[c], off);
        }
    }
    if (lane == 0) {
        #pragma unroll
        for (int c = 0; c < HIDD; c++) {
            attn_s[c * 16 + r0] = pa0[c];
            attn_s[c * 16 + r1] = pa1[c];
        }
    }
    __syncthreads();

    if (tid < 48) {
        int o = tid >> 4, r = tid & 15;
        float a = 0.f;
        #pragma unroll
        for (int c = 0; c < HIDD; c++) a += W3[o * HIDD + c] * attn_s[c * 16 + r];
        g_A3[((size_t)b * 3 + o) * EDIM + e0 + r] = a;
    }
}

// ---------------------------------------------------------------------------
// Stage 3: out[b,o,t] = p[b,o,t] + sum_e A3[b,o,e] Wo[t,e] + rowsum(W3)[o]*bo[t]
// Re-tiled for Wo reuse: CTA = 512 t-block x 8-batch chunk; A3 chunk in smem.
// ---------------------------------------------------------------------------
__global__ __launch_bounds__(256) void final2(
    const float* __restrict__ x, const float* __restrict__ Wo,
    const float* __restrict__ bo, const float* __restrict__ W3,
    float* __restrict__ out)
{
    __shared__ float a3s[8 * 3 * EDIM];   // 48 KB
    int tid = threadIdx.x;
    int b0 = blockIdx.y * 8;
    int ta = blockIdx.x * 512 + tid;
    int tb = ta + 256;

    for (int i = tid; i < 8 * 3 * EDIM; i += 256)
        a3s[i] = g_A3[(size_t)b0 * 3 * EDIM + i];

    float w3s[3];
    #pragma unroll
    for (int o = 0; o < 3; o++) {
        float s = 0.f;
        #pragma unroll
        for (int c = 0; c < HIDD; c++) s += W3[o * HIDD + c];
        w3s[o] = s;
    }
    __syncthreads();

    const float4* wra = (const float4*)(Wo + (size_t)ta * EDIM);
    const float4* wrb = (const float4*)(Wo + (size_t)tb * EDIM);
    const float4* a3v = (const float4*)a3s;

    float acc0[8][3], acc1[8][3];
    #pragma unroll
    for (int bb = 0; bb < 8; bb++)
        #pragma unroll
        for (int o = 0; o < 3; o++) { acc0[bb][o] = 0.f; acc1[bb][o] = 0.f; }

    for (int e = 0; e < EDIM / 4; e++) {
        float4 wa = wra[e];
        float4 wb = wrb[e];
        #pragma unroll
        for (int bb = 0; bb < 8; bb++)
            #pragma unroll
            for (int o = 0; o < 3; o++) {
                float4 v = a3v[(bb * 3 + o) * (EDIM / 4) + e];
                acc0[bb][o] += wa.x * v.x + wa.y * v.y + wa.z * v.z + wa.w * v.w;
                acc1[bb][o] += wb.x * v.x + wb.y * v.y + wb.z * v.z + wb.w * v.w;
            }
    }

    float boa = bo[ta], bob = bo[tb];
    #pragma unroll
    for (int bb = 0; bb < 8; bb++)
        #pragma unroll
        for (int o = 0; o < 3; o++) {
            size_t ob = ((size_t)(b0 + bb) * 3 + o) * TDIM;
            size_t xb = ((size_t)(b0 + bb) * 7 + o) * TDIM;
            out[ob + ta] = x[xb + ta] + acc0[bb][o] + w3s[o] * boa;
            out[ob + tb] = x[xb + tb] + acc1[bb][o] + w3s[o] * bob;
        }
}

// ---------------------------------------------------------------------------
extern "C" void kernel_launch(void* const* d_in, const int* in_sizes, int n_in,
                              void* d_out, int out_size)
{
    const float* x  = (const float*)d_in[0];
    const float* W1 = (const float*)d_in[1];
    const float* W2 = (const float*)d_in[2];
    const float* Wq = (const float*)d_in[3];
    const float* bq = (const float*)d_in[4];
    const float* Wk = (const float*)d_in[5];
    const float* bk = (const float*)d_in[6];
    const float* Wv = (const float*)d_in[7];
    const float* bv = (const float*)d_in[8];
    const float* Wo = (const float*)d_in[9];
    const float* bo = (const float*)d_in[10];
    const float* W3 = (const float*)d_in[11];
    float* out = (float*)d_out;

    stage1_mma<<<dim3(24, KS), 512, SMEM_S1>>>(x, Wq, Wk, Wv);
    qkv_kernel<<<BDIM, 256>>>(W1, W2, bq, bk, bv);
    attn_kernel<<<dim3(BDIM, EDIM / 16), 256>>>(W3);
    final2<<<dim3(TDIM / 512, BDIM / 8), 256>>>(x, Wo, bo, W3, out);
}